// round 11
// baseline (speedup 1.0000x reference)
#include <cuda_runtime.h>
#include <cuda_fp16.h>

#define NUM_USERS 100000
#define NUM_ITEMS 50000
#define N_NODES   150000
#define DIM       64
#define NUM_EDGES 4000000

// Scratch (allocation-free rule: __device__ globals).
__device__ __half2 g_bufA[N_NODES * DIM / 2];   // emb_fp16, then l2
__device__ __half2 g_bufB[N_NODES * DIM / 2];   // l1
__device__ __half2 g_bufC[N_NODES * DIM / 2];   // l3
__device__ int2    g_edges[NUM_EDGES];          // interleaved {col, val-bits}
__device__ int     g_hist[N_NODES];             // zero-init; re-zeroed by scan
__device__ int     g_rowptr[N_NODES + 1];
__device__ int     g_cursor[N_NODES];

// -------------------------------------------------------------------------
// Kernel 1 (fused): convert concat(user,item) -> fp16 bufA  AND  degree
// histogram (8 edges/thread).  g_hist is zero on entry: static init on the
// first call, re-zeroed by lgcn_scan on every subsequent replay.
// -------------------------------------------------------------------------
__global__ void lgcn_convert_hist(const float* __restrict__ user_emb,
                                  const float* __restrict__ item_emb,
                                  const int*   __restrict__ edge_row)
{
    int i = blockIdx.x * blockDim.x + threadIdx.x;
    const int total8 = N_NODES * DIM / 8;
    if (i < total8) {
        const int user8 = NUM_USERS * DIM / 8;
        const float4* s = (i < user8)
            ? (const float4*)user_emb + 2 * (size_t)i
            : (const float4*)item_emb + 2 * (size_t)(i - user8);
        float4 a = s[0];
        float4 b = s[1];
        __half2 h0 = __floats2half2_rn(a.x, a.y);
        __half2 h1 = __floats2half2_rn(a.z, a.w);
        __half2 h2 = __floats2half2_rn(b.x, b.y);
        __half2 h3 = __floats2half2_rn(b.z, b.w);
        uint4 p;
        p.x = *(unsigned int*)&h0;
        p.y = *(unsigned int*)&h1;
        p.z = *(unsigned int*)&h2;
        p.w = *(unsigned int*)&h3;
        ((uint4*)g_bufA)[i] = p;
    }
    if (i < NUM_EDGES / 8) {
        int4 r0 = __ldcs((const int4*)edge_row + i * 2);
        int4 r1 = __ldcs((const int4*)edge_row + i * 2 + 1);
        atomicAdd(&g_hist[r0.x], 1);
        atomicAdd(&g_hist[r0.y], 1);
        atomicAdd(&g_hist[r0.z], 1);
        atomicAdd(&g_hist[r0.w], 1);
        atomicAdd(&g_hist[r1.x], 1);
        atomicAdd(&g_hist[r1.y], 1);
        atomicAdd(&g_hist[r1.z], 1);
        atomicAdd(&g_hist[r1.w], 1);
    }
}

// -------------------------------------------------------------------------
// Kernel 2: single-block exclusive scan -> row_ptr + cursor.
// Re-zeroes g_hist after use so the next graph replay starts clean.
// -------------------------------------------------------------------------
__global__ void lgcn_scan()
{
    const int T = 1024;
    const int CHUNK = (N_NODES + T - 1) / T;   // 147
    __shared__ int s_part[T];

    int t   = threadIdx.x;
    int beg = t * CHUNK;
    int end = min(beg + CHUNK, N_NODES);

    int sum = 0;
    for (int i = beg; i < end; i++) sum += g_hist[i];
    s_part[t] = sum;
    __syncthreads();

    for (int off = 1; off < T; off <<= 1) {
        int v = (t >= off) ? s_part[t - off] : 0;
        __syncthreads();
        s_part[t] += v;
        __syncthreads();
    }

    int run = s_part[t] - sum;
    for (int i = beg; i < end; i++) {
        g_rowptr[i] = run;
        g_cursor[i] = run;
        run += g_hist[i];
        g_hist[i] = 0;          // ready for next replay
    }
    if (t == 0) g_rowptr[N_NODES] = NUM_EDGES;
}

// -------------------------------------------------------------------------
// Kernel 3: scatter edges into row-sorted interleaved array, 8 edges/thread.
// -------------------------------------------------------------------------
__global__ void lgcn_scatter(const float* __restrict__ edge_vals,
                             const int*   __restrict__ edge_row,
                             const int*   __restrict__ edge_col)
{
    int i = blockIdx.x * blockDim.x + threadIdx.x;
    if (i >= NUM_EDGES / 8) return;
    int4   r0 = __ldcs((const int4*)edge_row + i * 2);
    int4   r1 = __ldcs((const int4*)edge_row + i * 2 + 1);
    int4   c0 = __ldcs((const int4*)edge_col + i * 2);
    int4   c1 = __ldcs((const int4*)edge_col + i * 2 + 1);
    float4 v0 = __ldcs((const float4*)edge_vals + i * 2);
    float4 v1 = __ldcs((const float4*)edge_vals + i * 2 + 1);

    int p0 = atomicAdd(&g_cursor[r0.x], 1);
    int p1 = atomicAdd(&g_cursor[r0.y], 1);
    int p2 = atomicAdd(&g_cursor[r0.z], 1);
    int p3 = atomicAdd(&g_cursor[r0.w], 1);
    int p4 = atomicAdd(&g_cursor[r1.x], 1);
    int p5 = atomicAdd(&g_cursor[r1.y], 1);
    int p6 = atomicAdd(&g_cursor[r1.z], 1);
    int p7 = atomicAdd(&g_cursor[r1.w], 1);

    __stcs(&g_edges[p0], make_int2(c0.x, __float_as_int(v0.x)));
    __stcs(&g_edges[p1], make_int2(c0.y, __float_as_int(v0.y)));
    __stcs(&g_edges[p2], make_int2(c0.z, __float_as_int(v0.z)));
    __stcs(&g_edges[p3], make_int2(c0.w, __float_as_int(v0.w)));
    __stcs(&g_edges[p4], make_int2(c1.x, __float_as_int(v1.x)));
    __stcs(&g_edges[p5], make_int2(c1.y, __float_as_int(v1.y)));
    __stcs(&g_edges[p6], make_int2(c1.z, __float_as_int(v1.z)));
    __stcs(&g_edges[p7], make_int2(c1.w, __float_as_int(v1.w)));
}

// -------------------------------------------------------------------------
// Kernel 4: PURE warp-per-node CSR gather (R7-proven loop), fp16 in/out.
// No out RMW — result only to nxt.
// -------------------------------------------------------------------------
__global__ void __launch_bounds__(256)
lgcn_gather(const __half2* __restrict__ cur,
            __half2*       __restrict__ nxt)
{
    __shared__ int2 s_edges[8][32];
    const int wslot = threadIdx.x >> 5;
    const int lane  = threadIdx.x & 31;
    const int node  = blockIdx.x * 8 + wslot;
    if (node >= N_NODES) return;

    const int start = g_rowptr[node];
    const int end   = g_rowptr[node + 1];

    float2 acc = make_float2(0.f, 0.f);

    for (int base = start; base < end; base += 32) {
        int idx = base + lane;
        if (idx < end) s_edges[wslot][lane] = __ldcs(&g_edges[idx]);
        __syncwarp();
        const int n = min(32, end - base);
        #pragma unroll 8
        for (int j = 0; j < n; j++) {
            int2  cv = s_edges[wslot][j];
            float vj = __int_as_float(cv.y);
            __half2 x = cur[(size_t)cv.x * (DIM / 2) + lane];
            float2 xf = __half22float2(x);
            acc.x += vj * xf.x;
            acc.y += vj * xf.y;
        }
        __syncwarp();
    }

    nxt[(size_t)node * (DIM / 2) + lane] = __floats2half2_rn(acc.x, acc.y);
}

// -------------------------------------------------------------------------
// Kernel 5: final combine — out = 0.25 * (emb_f32 + l1 + l2 + l3).
// One streaming pass; 8 dims per thread.
// -------------------------------------------------------------------------
__global__ void lgcn_final(const float* __restrict__ user_emb,
                           const float* __restrict__ item_emb,
                           float*       __restrict__ out)
{
    int i = blockIdx.x * blockDim.x + threadIdx.x;
    const int total8 = N_NODES * DIM / 8;
    if (i >= total8) return;

    const int user8 = NUM_USERS * DIM / 8;
    const float4* s = (i < user8)
        ? (const float4*)user_emb + 2 * (size_t)i
        : (const float4*)item_emb + 2 * (size_t)(i - user8);
    float4 e0 = __ldcs(s);
    float4 e1 = __ldcs(s + 1);

    uint4 a = __ldcs((const uint4*)g_bufB + i);   // l1
    uint4 b = __ldcs((const uint4*)g_bufA + i);   // l2
    uint4 c = __ldcs((const uint4*)g_bufC + i);   // l3

    float2 s0, s1, s2, s3;   // pairwise sums of the three fp16 layers
    {
        float2 xa, xb, xc;
        xa = __half22float2(*(__half2*)&a.x);
        xb = __half22float2(*(__half2*)&b.x);
        xc = __half22float2(*(__half2*)&c.x);
        s0 = make_float2(xa.x + xb.x + xc.x, xa.y + xb.y + xc.y);
        xa = __half22float2(*(__half2*)&a.y);
        xb = __half22float2(*(__half2*)&b.y);
        xc = __half22float2(*(__half2*)&c.y);
        s1 = make_float2(xa.x + xb.x + xc.x, xa.y + xb.y + xc.y);
        xa = __half22float2(*(__half2*)&a.z);
        xb = __half22float2(*(__half2*)&b.z);
        xc = __half22float2(*(__half2*)&c.z);
        s2 = make_float2(xa.x + xb.x + xc.x, xa.y + xb.y + xc.y);
        xa = __half22float2(*(__half2*)&a.w);
        xb = __half22float2(*(__half2*)&b.w);
        xc = __half22float2(*(__half2*)&c.w);
        s3 = make_float2(xa.x + xb.x + xc.x, xa.y + xb.y + xc.y);
    }

    float4 o0 = make_float4((e0.x + s0.x) * 0.25f, (e0.y + s0.y) * 0.25f,
                            (e0.z + s1.x) * 0.25f, (e0.w + s1.y) * 0.25f);
    float4 o1 = make_float4((e1.x + s2.x) * 0.25f, (e1.y + s2.y) * 0.25f,
                            (e1.z + s3.x) * 0.25f, (e1.w + s3.y) * 0.25f);
    __stcs((float4*)out + 2 * (size_t)i,     o0);
    __stcs((float4*)out + 2 * (size_t)i + 1, o1);
}

// -------------------------------------------------------------------------
// Launch: 7 kernels, graph-capturable, no sync, no alloc.
// -------------------------------------------------------------------------
extern "C" void kernel_launch(void* const* d_in, const int* in_sizes, int n_in,
                              void* d_out, int out_size)
{
    const float* user_emb  = (const float*)d_in[0];
    const float* item_emb  = (const float*)d_in[1];
    const float* edge_vals = (const float*)d_in[2];
    const int*   edge_row  = (const int*)d_in[3];
    const int*   edge_col  = (const int*)d_in[4];
    float* out = (float*)d_out;

    __half2 *bufA, *bufB, *bufC;
    cudaGetSymbolAddress((void**)&bufA, g_bufA);
    cudaGetSymbolAddress((void**)&bufB, g_bufB);
    cudaGetSymbolAddress((void**)&bufC, g_bufC);

    const int total8    = N_NODES * DIM / 8;                 // 1.2M
    const int conv_grid = (total8 + 255) / 256;
    const int e8_grid   = (NUM_EDGES / 8 + 255) / 256;
    const int gather_grid = (N_NODES + 7) / 8;               // 8 warps/block

    // Build fp16 input + CSR (re-done every replay: deterministic).
    lgcn_convert_hist<<<conv_grid, 256>>>(user_emb, item_emb, edge_row);
    lgcn_scan<<<1, 1024>>>();
    lgcn_scatter<<<e8_grid, 256>>>(edge_vals, edge_row, edge_col);

    // 3 pure propagation layers:  A(emb) -> B(l1) -> A(l2) -> C(l3).
    lgcn_gather<<<gather_grid, 256>>>(bufA, bufB);
    lgcn_gather<<<gather_grid, 256>>>(bufB, bufA);
    lgcn_gather<<<gather_grid, 256>>>(bufA, bufC);

    // out = 0.25 * (emb + l1 + l2 + l3)
    lgcn_final<<<conv_grid, 256>>>(user_emb, item_emb, out);
}

// round 12
// speedup vs baseline: 1.9977x; 1.9977x over previous
#include <cuda_runtime.h>
#include <cuda_fp16.h>

#define NUM_USERS 100000
#define NUM_ITEMS 50000
#define N_NODES   150000
#define DIM       64
#define NUM_EDGES 4000000

#define SCAN_ELEMS  1024
#define SCAN_BLOCKS ((N_NODES + SCAN_ELEMS - 1) / SCAN_ELEMS)   // 147
#define N_INT4      (N_NODES / 4)                               // 37500 (exact)

// Scratch (allocation-free rule: __device__ globals).
__device__ __half2 g_bufA[N_NODES * DIM / 2];   // emb_fp16, then l2
__device__ __half2 g_bufB[N_NODES * DIM / 2];   // l1
__device__ __half2 g_bufC[N_NODES * DIM / 2];   // l3
__device__ int2    g_edges[NUM_EDGES];          // interleaved {col, val-bits}
__device__ int     g_hist[N_NODES];             // zero-init; re-zeroed by scan3
__device__ int     g_rowptr[N_NODES + 1];
__device__ int     g_cursor[N_NODES];
__device__ int     g_blocksum[SCAN_BLOCKS];

// -------------------------------------------------------------------------
// Kernel 1 (fused): convert concat(user,item) -> fp16 bufA  AND  degree
// histogram (8 edges/thread).  g_hist is zero on entry (static init first
// call; re-zeroed coalesced by scan3 on every replay).
// -------------------------------------------------------------------------
__global__ void lgcn_convert_hist(const float* __restrict__ user_emb,
                                  const float* __restrict__ item_emb,
                                  const int*   __restrict__ edge_row)
{
    int i = blockIdx.x * blockDim.x + threadIdx.x;
    const int total8 = N_NODES * DIM / 8;
    if (i < total8) {
        const int user8 = NUM_USERS * DIM / 8;
        const float4* s = (i < user8)
            ? (const float4*)user_emb + 2 * (size_t)i
            : (const float4*)item_emb + 2 * (size_t)(i - user8);
        float4 a = s[0];
        float4 b = s[1];
        __half2 h0 = __floats2half2_rn(a.x, a.y);
        __half2 h1 = __floats2half2_rn(a.z, a.w);
        __half2 h2 = __floats2half2_rn(b.x, b.y);
        __half2 h3 = __floats2half2_rn(b.z, b.w);
        uint4 p;
        p.x = *(unsigned int*)&h0;
        p.y = *(unsigned int*)&h1;
        p.z = *(unsigned int*)&h2;
        p.w = *(unsigned int*)&h3;
        ((uint4*)g_bufA)[i] = p;
    }
    if (i < NUM_EDGES / 8) {
        int4 r0 = __ldcs((const int4*)edge_row + i * 2);
        int4 r1 = __ldcs((const int4*)edge_row + i * 2 + 1);
        atomicAdd(&g_hist[r0.x], 1);
        atomicAdd(&g_hist[r0.y], 1);
        atomicAdd(&g_hist[r0.z], 1);
        atomicAdd(&g_hist[r0.w], 1);
        atomicAdd(&g_hist[r1.x], 1);
        atomicAdd(&g_hist[r1.y], 1);
        atomicAdd(&g_hist[r1.z], 1);
        atomicAdd(&g_hist[r1.w], 1);
    }
}

// -------------------------------------------------------------------------
// Scan pass 1: per-block sums of g_hist (1024 elements / block, int4).
// -------------------------------------------------------------------------
__global__ void lgcn_scan1()
{
    __shared__ int s_warp[8];
    int t = threadIdx.x;                 // 256
    int idx4 = blockIdx.x * 256 + t;
    int4 v = (idx4 < N_INT4) ? ((const int4*)g_hist)[idx4]
                             : make_int4(0, 0, 0, 0);
    int s = v.x + v.y + v.z + v.w;
    #pragma unroll
    for (int o = 16; o > 0; o >>= 1)
        s += __shfl_xor_sync(0xffffffffu, s, o);
    if ((t & 31) == 0) s_warp[t >> 5] = s;
    __syncthreads();
    if (t < 8) {
        int w = s_warp[t];
        #pragma unroll
        for (int o = 4; o > 0; o >>= 1)
            w += __shfl_xor_sync(0xffu, w, o);
        if (t == 0) g_blocksum[blockIdx.x] = w;
    }
}

// -------------------------------------------------------------------------
// Scan pass 2: one block scans the 147 block sums -> exclusive offsets.
// -------------------------------------------------------------------------
__global__ void lgcn_scan2()
{
    __shared__ int s_data[256];
    int t = threadIdx.x;                 // 256
    int v = (t < SCAN_BLOCKS) ? g_blocksum[t] : 0;
    s_data[t] = v;
    __syncthreads();
    #pragma unroll
    for (int o = 1; o < 256; o <<= 1) {
        int u = (t >= o) ? s_data[t - o] : 0;
        __syncthreads();
        s_data[t] += u;
        __syncthreads();
    }
    if (t < SCAN_BLOCKS) g_blocksum[t] = s_data[t] - v;   // exclusive
}

// -------------------------------------------------------------------------
// Scan pass 3: per-block exclusive scan -> rowptr + cursor (int4 writes),
// re-zero hist (coalesced) for the next replay.
// -------------------------------------------------------------------------
__global__ void lgcn_scan3()
{
    __shared__ int s_data[256];
    int t = threadIdx.x;                 // 256
    int idx4 = blockIdx.x * 256 + t;
    bool ok = (idx4 < N_INT4);
    int4 v = ok ? ((const int4*)g_hist)[idx4] : make_int4(0, 0, 0, 0);
    int s = v.x + v.y + v.z + v.w;

    s_data[t] = s;
    __syncthreads();
    #pragma unroll
    for (int o = 1; o < 256; o <<= 1) {
        int u = (t >= o) ? s_data[t - o] : 0;
        __syncthreads();
        s_data[t] += u;
        __syncthreads();
    }
    int off = g_blocksum[blockIdx.x] + s_data[t] - s;   // exclusive prefix

    if (ok) {
        int4 r;
        r.x = off;
        r.y = off + v.x;
        r.z = off + v.x + v.y;
        r.w = off + v.x + v.y + v.z;
        ((int4*)g_rowptr)[idx4] = r;    // g_rowptr[0..N_NODES) int4-aligned
        ((int4*)g_cursor)[idx4] = r;
        ((int4*)g_hist)[idx4] = make_int4(0, 0, 0, 0);
    }
    if (blockIdx.x == 0 && t == 0) g_rowptr[N_NODES] = NUM_EDGES;
}

// -------------------------------------------------------------------------
// Kernel 3: scatter edges into row-sorted interleaved array, 8 edges/thread.
// -------------------------------------------------------------------------
__global__ void lgcn_scatter(const float* __restrict__ edge_vals,
                             const int*   __restrict__ edge_row,
                             const int*   __restrict__ edge_col)
{
    int i = blockIdx.x * blockDim.x + threadIdx.x;
    if (i >= NUM_EDGES / 8) return;
    int4   r0 = __ldcs((const int4*)edge_row + i * 2);
    int4   r1 = __ldcs((const int4*)edge_row + i * 2 + 1);
    int4   c0 = __ldcs((const int4*)edge_col + i * 2);
    int4   c1 = __ldcs((const int4*)edge_col + i * 2 + 1);
    float4 v0 = __ldcs((const float4*)edge_vals + i * 2);
    float4 v1 = __ldcs((const float4*)edge_vals + i * 2 + 1);

    int p0 = atomicAdd(&g_cursor[r0.x], 1);
    int p1 = atomicAdd(&g_cursor[r0.y], 1);
    int p2 = atomicAdd(&g_cursor[r0.z], 1);
    int p3 = atomicAdd(&g_cursor[r0.w], 1);
    int p4 = atomicAdd(&g_cursor[r1.x], 1);
    int p5 = atomicAdd(&g_cursor[r1.y], 1);
    int p6 = atomicAdd(&g_cursor[r1.z], 1);
    int p7 = atomicAdd(&g_cursor[r1.w], 1);

    __stcs(&g_edges[p0], make_int2(c0.x, __float_as_int(v0.x)));
    __stcs(&g_edges[p1], make_int2(c0.y, __float_as_int(v0.y)));
    __stcs(&g_edges[p2], make_int2(c0.z, __float_as_int(v0.z)));
    __stcs(&g_edges[p3], make_int2(c0.w, __float_as_int(v0.w)));
    __stcs(&g_edges[p4], make_int2(c1.x, __float_as_int(v1.x)));
    __stcs(&g_edges[p5], make_int2(c1.y, __float_as_int(v1.y)));
    __stcs(&g_edges[p6], make_int2(c1.z, __float_as_int(v1.z)));
    __stcs(&g_edges[p7], make_int2(c1.w, __float_as_int(v1.w)));
}

// -------------------------------------------------------------------------
// Kernel 4: PURE warp-per-node CSR gather (R7-proven loop), fp16 in/out.
// -------------------------------------------------------------------------
__global__ void __launch_bounds__(256)
lgcn_gather(const __half2* __restrict__ cur,
            __half2*       __restrict__ nxt)
{
    __shared__ int2 s_edges[8][32];
    const int wslot = threadIdx.x >> 5;
    const int lane  = threadIdx.x & 31;
    const int node  = blockIdx.x * 8 + wslot;
    if (node >= N_NODES) return;

    const int start = g_rowptr[node];
    const int end   = g_rowptr[node + 1];

    float2 acc = make_float2(0.f, 0.f);

    for (int base = start; base < end; base += 32) {
        int idx = base + lane;
        if (idx < end) s_edges[wslot][lane] = __ldcs(&g_edges[idx]);
        __syncwarp();
        const int n = min(32, end - base);
        #pragma unroll 8
        for (int j = 0; j < n; j++) {
            int2  cv = s_edges[wslot][j];
            float vj = __int_as_float(cv.y);
            __half2 x = cur[(size_t)cv.x * (DIM / 2) + lane];
            float2 xf = __half22float2(x);
            acc.x += vj * xf.x;
            acc.y += vj * xf.y;
        }
        __syncwarp();
    }

    nxt[(size_t)node * (DIM / 2) + lane] = __floats2half2_rn(acc.x, acc.y);
}

// -------------------------------------------------------------------------
// Kernel 5: final combine — out = 0.25 * (emb_f32 + l1 + l2 + l3).
// -------------------------------------------------------------------------
__global__ void lgcn_final(const float* __restrict__ user_emb,
                           const float* __restrict__ item_emb,
                           float*       __restrict__ out)
{
    int i = blockIdx.x * blockDim.x + threadIdx.x;
    const int total8 = N_NODES * DIM / 8;
    if (i >= total8) return;

    const int user8 = NUM_USERS * DIM / 8;
    const float4* s = (i < user8)
        ? (const float4*)user_emb + 2 * (size_t)i
        : (const float4*)item_emb + 2 * (size_t)(i - user8);
    float4 e0 = __ldcs(s);
    float4 e1 = __ldcs(s + 1);

    uint4 a = __ldcs((const uint4*)g_bufB + i);   // l1
    uint4 b = __ldcs((const uint4*)g_bufA + i);   // l2
    uint4 c = __ldcs((const uint4*)g_bufC + i);   // l3

    float2 s0, s1, s2, s3;
    {
        float2 xa, xb, xc;
        xa = __half22float2(*(__half2*)&a.x);
        xb = __half22float2(*(__half2*)&b.x);
        xc = __half22float2(*(__half2*)&c.x);
        s0 = make_float2(xa.x + xb.x + xc.x, xa.y + xb.y + xc.y);
        xa = __half22float2(*(__half2*)&a.y);
        xb = __half22float2(*(__half2*)&b.y);
        xc = __half22float2(*(__half2*)&c.y);
        s1 = make_float2(xa.x + xb.x + xc.x, xa.y + xb.y + xc.y);
        xa = __half22float2(*(__half2*)&a.z);
        xb = __half22float2(*(__half2*)&b.z);
        xc = __half22float2(*(__half2*)&c.z);
        s2 = make_float2(xa.x + xb.x + xc.x, xa.y + xb.y + xc.y);
        xa = __half22float2(*(__half2*)&a.w);
        xb = __half22float2(*(__half2*)&b.w);
        xc = __half22float2(*(__half2*)&c.w);
        s3 = make_float2(xa.x + xb.x + xc.x, xa.y + xb.y + xc.y);
    }

    float4 o0 = make_float4((e0.x + s0.x) * 0.25f, (e0.y + s0.y) * 0.25f,
                            (e0.z + s1.x) * 0.25f, (e0.w + s1.y) * 0.25f);
    float4 o1 = make_float4((e1.x + s2.x) * 0.25f, (e1.y + s2.y) * 0.25f,
                            (e1.z + s3.x) * 0.25f, (e1.w + s3.y) * 0.25f);
    __stcs((float4*)out + 2 * (size_t)i,     o0);
    __stcs((float4*)out + 2 * (size_t)i + 1, o1);
}

// -------------------------------------------------------------------------
// Launch: 9 kernels, graph-capturable, no sync, no alloc.
// -------------------------------------------------------------------------
extern "C" void kernel_launch(void* const* d_in, const int* in_sizes, int n_in,
                              void* d_out, int out_size)
{
    const float* user_emb  = (const float*)d_in[0];
    const float* item_emb  = (const float*)d_in[1];
    const float* edge_vals = (const float*)d_in[2];
    const int*   edge_row  = (const int*)d_in[3];
    const int*   edge_col  = (const int*)d_in[4];
    float* out = (float*)d_out;

    __half2 *bufA, *bufB, *bufC;
    cudaGetSymbolAddress((void**)&bufA, g_bufA);
    cudaGetSymbolAddress((void**)&bufB, g_bufB);
    cudaGetSymbolAddress((void**)&bufC, g_bufC);

    const int total8    = N_NODES * DIM / 8;                 // 1.2M
    const int conv_grid = (total8 + 255) / 256;
    const int e8_grid   = (NUM_EDGES / 8 + 255) / 256;
    const int gather_grid = (N_NODES + 7) / 8;               // 8 warps/block

    // Build fp16 input + CSR (re-done every replay: deterministic).
    lgcn_convert_hist<<<conv_grid, 256>>>(user_emb, item_emb, edge_row);
    lgcn_scan1<<<SCAN_BLOCKS, 256>>>();
    lgcn_scan2<<<1, 256>>>();
    lgcn_scan3<<<SCAN_BLOCKS, 256>>>();
    lgcn_scatter<<<e8_grid, 256>>>(edge_vals, edge_row, edge_col);

    // 3 pure propagation layers:  A(emb) -> B(l1) -> A(l2) -> C(l3).
    lgcn_gather<<<gather_grid, 256>>>(bufA, bufB);
    lgcn_gather<<<gather_grid, 256>>>(bufB, bufA);
    lgcn_gather<<<gather_grid, 256>>>(bufA, bufC);

    // out = 0.25 * (emb + l1 + l2 + l3)
    lgcn_final<<<conv_grid, 256>>>(user_emb, item_emb, out);
}